// round 17
// baseline (speedup 1.0000x reference)
#include <cuda_runtime.h>
#include <math.h>

#define NBINS 1001
#define KQ 127
#define HALFB 500
#define EPS_S 1e-4
#define IMIN 63
#define NCAND 438
#define HIST_SUB 4
#define EXP_CUT -80.0
#define BAND 2e-3f
#define MAIN_GRID 592
#define KL_WARPS 4
#define KL_BLOCKS ((NCAND + KL_WARPS - 1) / KL_WARPS)   // 110

__device__ unsigned int g_absmax_bits;
__device__ unsigned int g_hist[NBINS];
__device__ unsigned int g_csum[NBINS + 1];
__device__ unsigned int g_total;
__device__ unsigned int g_bar;
__device__ unsigned int g_done;
__device__ unsigned int g_done2;
__device__ double g_kl[NCAND];

// ---------------- binning ----------------
__device__ __forceinline__ int bin_of(float c, float a, float inv, float step) {
    float y = __fmul_rn(__fadd_rn(c, a), inv);
    int b = (int)y;
    float fr = y - (float)b;
    if (fr < BAND || fr > 1.0f - BAND) {
        float e0 = __fadd_rn(__fmul_rn((float)b, step), -a);
        float e1 = __fadd_rn(__fmul_rn((float)(b + 1), step), -a);
        b += (c >= e1) ? 1 : 0;
        b -= (c < e0) ? 1 : 0;
    }
    return max(0, min(NBINS - 1, b));
}

// ---------------- fused absmax + grid barrier + histogram + scan (EXACT R10) ----------------
__global__ void __launch_bounds__(256, 4) main_kernel(const float* __restrict__ x, int n) {
    __shared__ unsigned int sh[HIST_SUB][NBINS];
    unsigned int* shf = &sh[0][0];
    for (int k = threadIdx.x; k < HIST_SUB * NBINS; k += 256) shf[k] = 0u;

    const int n4 = n >> 2;
    const float4* x4 = (const float4*)x;
    const int G = gridDim.x;
    const int b = blockIdx.x;
    const int lo = (int)((long long)b * n4 / G);
    const int hi = (int)((long long)(b + 1) * n4 / G);
    int lane = threadIdx.x & 31, w = threadIdx.x >> 5;

    float m = 0.f;
    for (int idx = lo + threadIdx.x; idx < hi; idx += 256) {
        float4 v = x4[idx];
        m = fmaxf(m, fmaxf(fmaxf(fabsf(v.x), fabsf(v.y)), fmaxf(fabsf(v.z), fabsf(v.w))));
    }
    if (b == 0 && threadIdx.x < (n & 3))
        m = fmaxf(m, fabsf(x[n4 * 4 + threadIdx.x]));
    #pragma unroll
    for (int o = 16; o; o >>= 1) m = fmaxf(m, __shfl_xor_sync(0xffffffffu, m, o));
    __shared__ float sm[8];
    if (lane == 0) sm[w] = m;
    __syncthreads();
    if (w == 0) {
        m = (lane < 8) ? sm[lane] : 0.f;
        #pragma unroll
        for (int o = 4; o; o >>= 1) m = fmaxf(m, __shfl_xor_sync(0xffffffffu, m, o));
        if (lane == 0) atomicMax(&g_absmax_bits, __float_as_uint(m));
    }

    __threadfence();
    __syncthreads();
    if (threadIdx.x == 0) {
        atomicAdd(&g_bar, 1u);
        while (*(volatile unsigned int*)&g_bar < (unsigned int)G) { }
    }
    __syncthreads();

    const float a = __uint_as_float(*(volatile unsigned int*)&g_absmax_bits);
    const float step = __fdiv_rn(__fmul_rn(2.0f, a), (float)NBINS);
    const float inv = __fdiv_rn((float)NBINS, __fmul_rn(2.0f, a));
    unsigned int* hsub = sh[(threadIdx.x >> 5) & (HIST_SUB - 1)];

    for (int idx = hi - 1 - threadIdx.x; idx >= lo; idx -= 256) {
        float4 v = x4[idx];
        atomicAdd(&hsub[bin_of(v.x, a, inv, step)], 1u);
        atomicAdd(&hsub[bin_of(v.y, a, inv, step)], 1u);
        atomicAdd(&hsub[bin_of(v.z, a, inv, step)], 1u);
        atomicAdd(&hsub[bin_of(v.w, a, inv, step)], 1u);
    }
    if (b == 0 && threadIdx.x < (n & 3)) {
        float c = x[n4 * 4 + threadIdx.x];
        atomicAdd(&hsub[bin_of(c, a, inv, step)], 1u);
    }
    __syncthreads();
    for (int k = threadIdx.x; k < NBINS; k += 256) {
        unsigned int s = 0;
        #pragma unroll
        for (int j = 0; j < HIST_SUB; j++) s += sh[j][k];
        if (s) atomicAdd(&g_hist[k], s);
    }

    __shared__ unsigned int s_last;
    __threadfence();
    if (threadIdx.x == 0)
        s_last = (atomicAdd(&g_done, 1u) == (unsigned int)(G - 1)) ? 1u : 0u;
    __syncthreads();
    if (s_last) {
        __threadfence();
        __shared__ unsigned int tsum[256];
        __shared__ unsigned int wex[9];
        int t = threadIdx.x;
        unsigned int hv[4], loc[4];
        unsigned int s = 0;
        #pragma unroll
        for (int j = 0; j < 4; j++) {
            int k = 4 * t + j;
            hv[j] = (k < NBINS) ? *(volatile unsigned int*)&g_hist[k] : 0u;
            loc[j] = s;
            s += hv[j];
        }
        tsum[t] = s;
        __syncthreads();
        unsigned int v = tsum[t];
        unsigned int inc = v;
        #pragma unroll
        for (int o = 1; o < 32; o <<= 1) {
            unsigned int q = __shfl_up_sync(0xffffffffu, inc, o);
            if (lane >= o) inc += q;
        }
        if (lane == 31) wex[w + 1] = inc;
        __syncthreads();
        if (t == 0) {
            wex[0] = 0u;
            for (int j = 1; j < 8; j++) wex[j + 1] += wex[j];
        }
        __syncthreads();
        unsigned int base = wex[w] + inc - v;
        #pragma unroll
        for (int j = 0; j < 4; j++) {
            int k = 4 * t + j;
            if (k < NBINS) g_csum[k] = base + loc[j];
        }
        if (t == 255) {
            unsigned int tot = base + loc[3] + hv[3];
            g_csum[NBINS] = tot;
            g_total = tot;
        }
    }
}

// ---------------- warp reductions ----------------
template <typename T>
__device__ __forceinline__ T warpSumT(T v) {
    #pragma unroll
    for (int o = 16; o; o >>= 1) v += __shfl_xor_sync(0xffffffffu, v, o);
    return v;
}
__device__ __forceinline__ unsigned int warpMaxU(unsigned int v) {
    #pragma unroll
    for (int o = 16; o; o >>= 1) v = max(v, __shfl_xor_sync(0xffffffffu, v, o));
    return v;
}
__device__ __forceinline__ double warpMaxD(double v) {
    #pragma unroll
    for (int o = 16; o; o >>= 1) v = fmax(v, __shfl_xor_sync(0xffffffffu, v, o));
    return v;
}

__device__ __forceinline__ double exp_fast(double x) {
    return (double)expf((float)x);
}

// ---------------- per-candidate KL: warp/candidate, register-resident bins ----------------
__global__ void __launch_bounds__(KL_WARPS * 32) kl_kernel(float* __restrict__ out) {
    __shared__ unsigned int s_h[NBINS];
    __shared__ double s_q[KL_WARPS][KQ + 1];
    const int lane = threadIdx.x & 31;
    const int wid = threadIdx.x >> 5;

    for (int k = threadIdx.x; k < NBINS; k += KL_WARPS * 32) s_h[k] = g_hist[k];
    __syncthreads();

    const int cand = (int)blockIdx.x * KL_WARPS + wid;
    if (cand < NCAND) {
        const int i = IMIN + cand;
        const int L = 2 * i + 1;
        const int start = HALFB - i;
        const int stop = HALFB + i + 1;
        const int m = L / KQ;                 // 1..7
        const unsigned int left = g_csum[start];
        const unsigned int right = g_total - g_csum[stop];
        double* q_w = s_q[wid];

        // ---- single sweep: bins -> registers (unrolled, pipelined LDS) + max p ----
        unsigned int pv[32];
        unsigned int mpi = 0u;
        #pragma unroll
        for (int j = 0; j < 32; j++) {
            int k = lane + (j << 5);
            unsigned int p = 0u;
            if (k < L) {
                p = s_h[start + k];
                if (k == 0) p += left;
                if (k == L - 1) p += right;
            }
            pv[j] = p;
            mpi = max(mpi, p);
        }
        mpi = warpMaxU(mpi);
        const double mp = mpi ? (double)mpi : EPS_S;

        // ---- regular segments s<126: lane owns s, s+32, s+64, s+96; length m<=7
        //      (their bins never reach k=L-1, so count test is just v!=0) ----
        double qs[4];
        unsigned int nms[4];
        unsigned int nnz = 0u;
        double mq = -1e300;
        #pragma unroll
        for (int si = 0; si < 4; si++) {
            int s = lane + si * 32;
            unsigned int sum = 0u, cnt = 0u;
            if (s < KQ - 1) {
                int k0 = start + s * m;
                #pragma unroll
                for (int jj = 0; jj < 7; jj++) {
                    if (jj < m) {
                        unsigned int v = s_h[k0 + jj];
                        sum += v;
                        cnt += (v != 0u);
                    }
                }
                double q = cnt ? (double)sum / (double)cnt : 0.0;
                q_w[s] = q;
                qs[si] = q; nms[si] = cnt;
                nnz += cnt;
                if (cnt) mq = fmax(mq, q);
            } else { qs[si] = 0.0; nms[si] = 0u; }
        }
        // ---- last segment (126): cooperative warp sum over [126*m, L) ----
        unsigned int lsum = 0u, lcnt = 0u;
        for (int k = (KQ - 1) * m + lane; k < L; k += 32) {
            unsigned int v = s_h[start + k];
            lsum += v;
            lcnt += (v != 0u && k != L - 1) ? 1u : 0u;
        }
        lsum = warpSumT(lsum);
        lcnt = warpSumT(lcnt);
        const double qlast = lcnt ? (double)lsum / (double)lcnt : 0.0;
        if (lane == 0) q_w[KQ - 1] = qlast;

        nnz = warpSumT(nnz) + lcnt;
        mq = warpMaxD(mq);
        if (lcnt) mq = fmax(mq, qlast);
        mq = fmax(mq, EPS_S);   // zero-q bins always exist (k=L-1)

        // ---- sq: grouped per-segment + zero-q bins ----
        double sq = 0.0;
        #pragma unroll
        for (int t = 0; t < 4; t++) {
            if (nms[t]) {
                double dq = qs[t] - mq;
                if (dq > EXP_CUT) sq += (double)nms[t] * exp_fast(dq);
            }
        }
        if (lane == 0) {
            if (lcnt) {
                double dq = qlast - mq;
                if (dq > EXP_CUT) sq += (double)lcnt * exp_fast(dq);
            }
            double dz = EPS_S - mq;
            if (dz > EXP_CUT) sq += (double)(L - (int)nnz) * exp_fast(dz);
        }
        // ---- sp from registers ----
        double sp = 0.0;
        {
            double gate = mp + EXP_CUT;
            #pragma unroll
            for (int j = 0; j < 32; j++) {
                int k = lane + (j << 5);
                if (k < L) {
                    double pl = pv[j] ? (double)pv[j] : EPS_S;
                    if (pl > gate) sp += exp_fast(pl - mp);
                }
            }
        }
        sp = warpSumT(sp);
        sq = warpSumT(sq);
        const double lZp = mp + (double)logf((float)sp);
        const double lZq = mq + (double)logf((float)sq);

        // ---- kl from registers ----
        double kl = 0.0;
        {
            double gate = lZp + EXP_CUT;
            #pragma unroll
            for (int j = 0; j < 32; j++) {
                int k = lane + (j << 5);
                if (k < L) {
                    double pl = pv[j] ? (double)pv[j] : EPS_S;
                    if (pl > gate) {
                        unsigned int vraw = pv[j];
                        if (k == 0) vraw -= left;
                        if (k == L - 1) vraw -= right;
                        int seg = min(k / m, KQ - 1);
                        bool assigned = (vraw != 0u) && (k != L - 1);
                        double ql = assigned ? q_w[seg] : EPS_S;
                        double lp = pl - lZp;
                        double lq = ql - lZq;
                        kl += exp_fast(lp) * (lp - lq);
                    }
                }
            }
        }
        kl = warpSumT(kl);
        if (lane == 0)
            g_kl[cand] = (nnz > 0u) ? kl : (double)INFINITY;
    }

    // ---- fused argmin + output + global-state reset (last block) ----
    __shared__ unsigned int s_fin;
    __syncthreads();
    __threadfence();
    if (threadIdx.x == 0)
        s_fin = (atomicAdd(&g_done2, 1u) == (unsigned int)(gridDim.x - 1)) ? 1u : 0u;
    __syncthreads();
    if (s_fin) {
        __threadfence();
        __shared__ double sv[KL_WARPS * 32];
        __shared__ int si2[KL_WARPS * 32];
        double best = (double)INFINITY;
        int bi = 0x7fffffff;
        for (int k = threadIdx.x; k < NCAND; k += KL_WARPS * 32) {
            double v = *(volatile double*)&g_kl[k];
            if (v < best || (v == best && k < bi)) { best = v; bi = k; }
        }
        sv[threadIdx.x] = best; si2[threadIdx.x] = bi;
        __syncthreads();
        for (int s = KL_WARPS * 16; s > 0; s >>= 1) {
            if (threadIdx.x < s) {
                double vo = sv[threadIdx.x + s];
                int io = si2[threadIdx.x + s];
                if (vo < sv[threadIdx.x] || (vo == sv[threadIdx.x] && io < si2[threadIdx.x])) {
                    sv[threadIdx.x] = vo; si2[threadIdx.x] = io;
                }
            }
            __syncthreads();
        }
        if (threadIdx.x == 0) {
            int ib = IMIN + si2[0];
            float a = __uint_as_float(g_absmax_bits);
            double thr = -(double)a + 2.0 * (double)a * (double)(ib + HALFB + 1) / (double)NBINS;
            out[0] = (float)thr;
            g_absmax_bits = 0u;
            g_bar = 0u;
            g_done = 0u;
            g_done2 = 0u;
        }
        for (int k = threadIdx.x; k < NBINS; k += KL_WARPS * 32) g_hist[k] = 0u;
    }
}

extern "C" void kernel_launch(void* const* d_in, const int* in_sizes, int n_in,
                              void* d_out, int out_size) {
    const float* x = (const float*)d_in[0];
    int n = in_sizes[0];
    main_kernel<<<MAIN_GRID, 256>>>(x, n);
    kl_kernel<<<KL_BLOCKS, KL_WARPS * 32>>>((float*)d_out);
}